// round 2
// baseline (speedup 1.0000x reference)
#include <cuda_runtime.h>
#include <math.h>

// ---------------------------------------------------------------------------
// PhaseQuantizer: 2-step residual phase quantization, minimal-traffic plan.
//   pass1: masked abs-sum stats of w              (reads 2n floats)
//   pass2: [inline reduce s1] eval q1, stats(err1) (reads 2n)
//   pass3: [inline reduce s1,s2] q1,q2 -> out      (reads 2n, writes 2n)
// Total HBM traffic 8n floats = 1.07 GB; evals are trimmed (~28 instr,
// 3 MUFU) via P-even/Q-odd symmetry + prescaled exp2 polynomial so every
// pass is at or near the memory roofline.
// ---------------------------------------------------------------------------

namespace {
constexpr int   NBLK  = 1184;   // 8 * 148 SMs, grid-stride
constexpr int   NTHR  = 256;
constexpr float PI_F  = 3.14159265358979323846f;
constexpr float LOG2E = 1.44269504088896340736f;
}

struct Part { float sre, sim; int cre, cim; };
__device__ Part g_part1[NBLK];
__device__ Part g_part2[NBLK];

__device__ __forceinline__ float ex2f(float x) {
    float y; asm("ex2.approx.f32 %0, %1;" : "=f"(y) : "f"(x)); return y;
}
__device__ __forceinline__ float rcpf(float x) {
    float y; asm("rcp.approx.f32 %0, %1;" : "=f"(y) : "f"(x)); return y;
}

// Per-thread uniform constants derived from temp.
struct Coef {
    float p0, p1, p2, p3, p4;  // atan poly coeffs prescaled by (pi/t)*log2(e)
    float c1, c3;              // exp(-pi^2/(4t)), exp(-pi^2/t)
};

__device__ __forceinline__ Coef make_coef(const float* temp) {
    float t = __ldg(temp) + 1e-6f;
    float inv_t = 1.0f / t;                 // full-precision, once per thread
    float kl = PI_F * inv_t * LOG2E;        // exp2 prescale
    Coef c;
    // Abramowitz & Stegun 4.4.49 atan poly (|x|<=1, |err|<=1e-5 rad)
    c.p0 =  0.9998660f * kl;
    c.p1 = -0.3302995f * kl;
    c.p2 =  0.1801410f * kl;
    c.p3 = -0.0851330f * kl;
    c.p4 =  0.0208351f * kl;
    c.c1 = __expf(-(PI_F * PI_F * 0.25f) * inv_t);
    c.c3 = c.c1 * c.c1; c.c3 = c.c3 * c.c3;
    return c;
}

// Soft phase quantization of one complex value.
// Uses psi'' = atan(minor/|major|); P is even / Q is odd in psi, so all
// quadrant signs reduce to copysign(P, major) and Q's natural sign.
__device__ __forceinline__ void quant_eval(float re, float im,
                                           float sre, float sim,
                                           const Coef& c,
                                           float& qre, float& qim) {
    float ar = fabsf(re), ai = fabsf(im);
    bool  rd = (ar >= ai);
    float m  = fmaxf(fmaxf(ar, ai), 1e-30f);
    float nm = rd ? im : re;
    float r  = nm * rcpf(m);
    float r2 = r * r;
    float p  = fmaf(r2, c.p4, c.p3);
    p = fmaf(r2, p, c.p2);
    p = fmaf(r2, p, c.p1);
    p = fmaf(r2, p, c.p0);
    float v   = r * p;                 // (pi/t)*log2e * psi
    float e   = ex2f(v);               // exp(+pi*psi/t)
    float ei  = rcpf(e);               // exp(-pi*psi/t)
    float sum = e + ei;
    float dif = e - ei;
    float em  = fmaxf(e, ei);          // exp(pi*|psi|/t)
    float uo  = (c.c3 * em) * em;      // opposite-center weight
    float D   = fmaf(c.c1, sum, 1.0f + uo);
    float rD  = rcpf(D);
    float P   = (1.0f - uo) * rD;      // p_near - p_opposite  (even)
    float Q   = (c.c1 * dif) * rD;     // p_+90  - p_-90       (odd)
    float majs = rd ? re : im;
    float qa  = copysignf(P, majs);
    float u   = rd ? qa : Q;
    float w   = rd ? Q  : qa;
    qre = u * sre;
    qim = w * sim;
}

__device__ __forceinline__ void acc_stats(float re, float im,
                                          float& sre, float& sim,
                                          int& cre, int& cim) {
    float ar = fabsf(re), ai = fabsf(im);
    if (ar >= ai) { sre += ar; cre++; }
    else          { sim += ai; cim++; }
}

// Deterministic fixed-order block reduce -> per-block partial slot.
__device__ __forceinline__ void stats_reduce_store(Part* part,
                                                   float sre, float sim,
                                                   int cre, int cim) {
    #pragma unroll
    for (int o = 16; o > 0; o >>= 1) {
        sre += __shfl_down_sync(0xffffffffu, sre, o);
        sim += __shfl_down_sync(0xffffffffu, sim, o);
        cre += __shfl_down_sync(0xffffffffu, cre, o);
        cim += __shfl_down_sync(0xffffffffu, cim, o);
    }
    __shared__ float sh_sre[NTHR / 32], sh_sim[NTHR / 32];
    __shared__ int   sh_cre[NTHR / 32], sh_cim[NTHR / 32];
    int lane = threadIdx.x & 31, wrp = threadIdx.x >> 5;
    if (lane == 0) { sh_sre[wrp] = sre; sh_sim[wrp] = sim;
                     sh_cre[wrp] = cre; sh_cim[wrp] = cim; }
    __syncthreads();
    if (threadIdx.x == 0) {
        float a = 0.f, b = 0.f; int cc = 0, d = 0;
        #pragma unroll
        for (int i = 0; i < NTHR / 32; i++) {
            a += sh_sre[i]; b += sh_sim[i]; cc += sh_cre[i]; d += sh_cim[i];
        }
        part[blockIdx.x].sre = a; part[blockIdx.x].sim = b;
        part[blockIdx.x].cre = cc; part[blockIdx.x].cim = d;
    }
}

// Inline final reduce over a partial buffer; every block computes the
// identical fixed-order result (deterministic). Returns (s_re, s_im).
__device__ __forceinline__ float2 final_reduce(const Part* __restrict__ part,
                                               float* sh_s, int* sh_c,
                                               float2* sh_res) {
    float sre = 0.f, sim = 0.f; int cre = 0, cim = 0;
    for (int i = threadIdx.x; i < NBLK; i += NTHR) {
        Part p = part[i];
        sre += p.sre; sim += p.sim; cre += p.cre; cim += p.cim;
    }
    #pragma unroll
    for (int o = 16; o > 0; o >>= 1) {
        sre += __shfl_down_sync(0xffffffffu, sre, o);
        sim += __shfl_down_sync(0xffffffffu, sim, o);
        cre += __shfl_down_sync(0xffffffffu, cre, o);
        cim += __shfl_down_sync(0xffffffffu, cim, o);
    }
    int lane = threadIdx.x & 31, wrp = threadIdx.x >> 5;
    if (lane == 0) {
        sh_s[wrp] = sre; sh_s[8 + wrp] = sim;
        sh_c[wrp] = cre; sh_c[8 + wrp] = cim;
    }
    __syncthreads();
    if (threadIdx.x == 0) {
        float a = 0.f, b = 0.f; int cc = 0, d = 0;
        #pragma unroll
        for (int i = 0; i < 8; i++) {
            a += sh_s[i]; b += sh_s[8 + i]; cc += sh_c[i]; d += sh_c[8 + i];
        }
        // s = max(sum / max(cnt,1), 1e-6); cnt==0 => sum==0 => clamps to 1e-6
        sh_res->x = fmaxf(a / fmaxf((float)cc, 1.0f), 1e-6f);
        sh_res->y = fmaxf(b / fmaxf((float)d, 1.0f), 1e-6f);
    }
    __syncthreads();
    return *sh_res;
}

// ---------------- Pass 1: stats of raw w -> g_part1 ----------------
__global__ void __launch_bounds__(NTHR)
k_pass1(const float* __restrict__ re, const float* __restrict__ im, int n) {
    float sre = 0.f, sim = 0.f; int cre = 0, cim = 0;
    int gtid = blockIdx.x * NTHR + threadIdx.x;
    int stride = gridDim.x * NTHR;
    int n4 = n >> 2;
    const float4* re4 = reinterpret_cast<const float4*>(re);
    const float4* im4 = reinterpret_cast<const float4*>(im);
    for (int i = gtid; i < n4; i += stride) {
        float4 a = re4[i], b = im4[i];
        acc_stats(a.x, b.x, sre, sim, cre, cim);
        acc_stats(a.y, b.y, sre, sim, cre, cim);
        acc_stats(a.z, b.z, sre, sim, cre, cim);
        acc_stats(a.w, b.w, sre, sim, cre, cim);
    }
    for (int i = (n4 << 2) + gtid; i < n; i += stride)
        acc_stats(re[i], im[i], sre, sim, cre, cim);
    stats_reduce_store(g_part1, sre, sim, cre, cim);
}

// ------- Pass 2: s1 = reduce(g_part1); stats of err1 -> g_part2 -------
__global__ void __launch_bounds__(NTHR)
k_pass2(const float* __restrict__ re, const float* __restrict__ im,
        const float* __restrict__ temp, int n) {
    __shared__ float  sh_s[16];
    __shared__ int    sh_c[16];
    __shared__ float2 sh_res;
    float2 s1 = final_reduce(g_part1, sh_s, sh_c, &sh_res);
    Coef c = make_coef(temp);

    float sre = 0.f, sim = 0.f; int cre = 0, cim = 0;
    int gtid = blockIdx.x * NTHR + threadIdx.x;
    int stride = gridDim.x * NTHR;
    int n4 = n >> 2;
    const float4* re4 = reinterpret_cast<const float4*>(re);
    const float4* im4 = reinterpret_cast<const float4*>(im);
    for (int i = gtid; i < n4; i += stride) {
        float4 a = re4[i], b = im4[i];
        float qr, qi;
        quant_eval(a.x, b.x, s1.x, s1.y, c, qr, qi);
        acc_stats(a.x - qr, b.x - qi, sre, sim, cre, cim);
        quant_eval(a.y, b.y, s1.x, s1.y, c, qr, qi);
        acc_stats(a.y - qr, b.y - qi, sre, sim, cre, cim);
        quant_eval(a.z, b.z, s1.x, s1.y, c, qr, qi);
        acc_stats(a.z - qr, b.z - qi, sre, sim, cre, cim);
        quant_eval(a.w, b.w, s1.x, s1.y, c, qr, qi);
        acc_stats(a.w - qr, b.w - qi, sre, sim, cre, cim);
    }
    for (int i = (n4 << 2) + gtid; i < n; i += stride) {
        float qr, qi;
        quant_eval(re[i], im[i], s1.x, s1.y, c, qr, qi);
        acc_stats(re[i] - qr, im[i] - qi, sre, sim, cre, cim);
    }
    stats_reduce_store(g_part2, sre, sim, cre, cim);
}

// ------- Pass 3: s1,s2 reduces; out = q1 + q2 -------
__global__ void __launch_bounds__(NTHR)
k_pass3(const float* __restrict__ re, const float* __restrict__ im,
        const float* __restrict__ temp,
        float* __restrict__ out_re, float* __restrict__ out_im, int n) {
    __shared__ float  sh_s[16];
    __shared__ int    sh_c[16];
    __shared__ float2 sh_res1, sh_res2;
    float2 s1 = final_reduce(g_part1, sh_s, sh_c, &sh_res1);
    __syncthreads();   // reuse of sh_s/sh_c between the two reduces
    float2 s2 = final_reduce(g_part2, sh_s, sh_c, &sh_res2);
    Coef c = make_coef(temp);

    int gtid = blockIdx.x * NTHR + threadIdx.x;
    int stride = gridDim.x * NTHR;
    int n4 = n >> 2;
    const float4* re4 = reinterpret_cast<const float4*>(re);
    const float4* im4 = reinterpret_cast<const float4*>(im);
    float4* or4 = reinterpret_cast<float4*>(out_re);
    float4* oi4 = reinterpret_cast<float4*>(out_im);
    for (int i = gtid; i < n4; i += stride) {
        float4 a = re4[i], b = im4[i];
        float4 qr4, qi4;
        float q1r, q1i, q2r, q2i;
        quant_eval(a.x, b.x, s1.x, s1.y, c, q1r, q1i);
        quant_eval(a.x - q1r, b.x - q1i, s2.x, s2.y, c, q2r, q2i);
        qr4.x = q1r + q2r; qi4.x = q1i + q2i;
        quant_eval(a.y, b.y, s1.x, s1.y, c, q1r, q1i);
        quant_eval(a.y - q1r, b.y - q1i, s2.x, s2.y, c, q2r, q2i);
        qr4.y = q1r + q2r; qi4.y = q1i + q2i;
        quant_eval(a.z, b.z, s1.x, s1.y, c, q1r, q1i);
        quant_eval(a.z - q1r, b.z - q1i, s2.x, s2.y, c, q2r, q2i);
        qr4.z = q1r + q2r; qi4.z = q1i + q2i;
        quant_eval(a.w, b.w, s1.x, s1.y, c, q1r, q1i);
        quant_eval(a.w - q1r, b.w - q1i, s2.x, s2.y, c, q2r, q2i);
        qr4.w = q1r + q2r; qi4.w = q1i + q2i;
        or4[i] = qr4;
        oi4[i] = qi4;
    }
    for (int i = (n4 << 2) + gtid; i < n; i += stride) {
        float q1r, q1i, q2r, q2i;
        quant_eval(re[i], im[i], s1.x, s1.y, c, q1r, q1i);
        quant_eval(re[i] - q1r, im[i] - q1i, s2.x, s2.y, c, q2r, q2i);
        out_re[i] = q1r + q2r;
        out_im[i] = q1i + q2i;
    }
}

extern "C" void kernel_launch(void* const* d_in, const int* in_sizes, int n_in,
                              void* d_out, int out_size) {
    const float* w_re = (const float*)d_in[0];
    const float* w_im = (const float*)d_in[1];
    const float* temp = (const float*)d_in[2];
    int n = in_sizes[0];
    float* out_re = (float*)d_out;
    float* out_im = out_re + n;

    k_pass1<<<NBLK, NTHR>>>(w_re, w_im, n);
    k_pass2<<<NBLK, NTHR>>>(w_re, w_im, temp, n);
    k_pass3<<<NBLK, NTHR>>>(w_re, w_im, temp, out_re, out_im, n);
}

// round 3
// speedup vs baseline: 1.0752x; 1.0752x over previous
#include <cuda_runtime.h>
#include <math.h>

// ---------------------------------------------------------------------------
// PhaseQuantizer: 2-step residual phase quantization, minimal-traffic plan.
//   pass1: masked abs-sum stats of w               (reads 8n bytes)
//   pass2: [inline reduce s1] eval q1, stats(err1)  (reads 8n)
//   pass3: [inline reduce s1,s2] q1,q2 -> out       (reads 8n, writes 8n)
// Eval uses psi>=0 + E=e^2 factorization: 3 MUFU / ~27 instr per eval.
// Memory loops are 2x-unrolled grid-stride for MLP.
// ---------------------------------------------------------------------------

namespace {
constexpr int   NBLK  = 1184;   // 8 * 148 SMs, grid-stride
constexpr int   NTHR  = 256;
constexpr float PI_F  = 3.14159265358979323846f;
constexpr float LOG2E = 1.44269504088896340736f;
}

struct Part { float sre, sim; int cre, cim; };
__device__ Part g_part1[NBLK];
__device__ Part g_part2[NBLK];

__device__ __forceinline__ float ex2f(float x) {
    float y; asm("ex2.approx.f32 %0, %1;" : "=f"(y) : "f"(x)); return y;
}
__device__ __forceinline__ float rcpf(float x) {
    float y; asm("rcp.approx.f32 %0, %1;" : "=f"(y) : "f"(x)); return y;
}

// Per-thread uniform constants derived from temp.
struct Coef {
    float p0, p1, p2, p3, p4;  // atan poly coeffs prescaled by (pi/t)*log2(e)
    float c1, c3;              // exp(-pi^2/(4t)), exp(-pi^2/t)
};

__device__ __forceinline__ Coef make_coef(const float* temp) {
    float t = __ldg(temp) + 1e-6f;
    float inv_t = 1.0f / t;
    float kl = PI_F * inv_t * LOG2E;        // exp2 prescale
    Coef c;
    // Abramowitz & Stegun 4.4.49 atan poly (|x|<=1, |err|<=1e-5 rad)
    c.p0 =  0.9998660f * kl;
    c.p1 = -0.3302995f * kl;
    c.p2 =  0.1801410f * kl;
    c.p3 = -0.0851330f * kl;
    c.p4 =  0.0208351f * kl;
    c.c1 = __expf(-(PI_F * PI_F * 0.25f) * inv_t);
    c.c3 = c.c1 * c.c1; c.c3 = c.c3 * c.c3;
    return c;
}

// Soft phase quantization of one complex value. psi = atan(min/max) >= 0,
// e = exp(pi*psi/t) >= 1, E = e^2; softmax factored so only 3 MUFU ops:
// rcp(maj), ex2(v), rcp(eD).  P even / Q odd in signed psi -> signs via
// copysign with major (P) and minor (Q).
__device__ __forceinline__ void quant_eval(float re, float im,
                                           float sre, float sim,
                                           const Coef& c,
                                           float& qre, float& qim) {
    float ar = fabsf(re), ai = fabsf(im);
    bool  rd = (ar >= ai);
    float m  = fmaxf(fmaxf(ar, ai), 1e-30f);
    float nm = fminf(ar, ai);
    float r  = nm * rcpf(m);               // in [0,1]
    float r2 = r * r;
    float p  = fmaf(r2, c.p4, c.p3);
    p = fmaf(r2, p, c.p2);
    p = fmaf(r2, p, c.p1);
    p = fmaf(r2, p, c.p0);
    float v  = r * p;                       // (pi/t)*log2e * psi  (>= 0)
    float e  = ex2f(v);                     // exp(pi*psi/t) >= 1
    float E  = e * e;
    float uo = c.c3 * E;                    // opposite-center weight
    float t2 = fmaf(e, uo, e);              // e*(1+uo)
    float eD = fmaf(c.c1, E + 1.0f, t2);    // e * softmax denominator
    float rD = rcpf(eD);
    float P  = (2.0f * e - t2) * rD;        // e*(1-uo)/eD = p_near - p_opp
    float Qa = fmaf(c.c1, E, -c.c1) * rD;   // c1*(E-1)/eD = p_+90 - p_-90
    float mins = rd ? im : re;              // signed minor
    float majs = rd ? re : im;              // signed major
    float Q  = copysignf(Qa, mins);
    float qa = copysignf(P, majs);
    float u  = rd ? qa : Q;
    float w  = rd ? Q  : qa;
    qre = u * sre;
    qim = w * sim;
}

__device__ __forceinline__ void acc_stats(float re, float im,
                                          float& sre, float& sim,
                                          int& cre, int& cim) {
    float ar = fabsf(re), ai = fabsf(im);
    if (ar >= ai) { sre += ar; cre++; }
    else          { sim += ai; cim++; }
}

// Deterministic fixed-order block reduce -> per-block partial slot.
__device__ __forceinline__ void stats_reduce_store(Part* part,
                                                   float sre, float sim,
                                                   int cre, int cim) {
    #pragma unroll
    for (int o = 16; o > 0; o >>= 1) {
        sre += __shfl_down_sync(0xffffffffu, sre, o);
        sim += __shfl_down_sync(0xffffffffu, sim, o);
        cre += __shfl_down_sync(0xffffffffu, cre, o);
        cim += __shfl_down_sync(0xffffffffu, cim, o);
    }
    __shared__ float sh_sre[NTHR / 32], sh_sim[NTHR / 32];
    __shared__ int   sh_cre[NTHR / 32], sh_cim[NTHR / 32];
    int lane = threadIdx.x & 31, wrp = threadIdx.x >> 5;
    if (lane == 0) { sh_sre[wrp] = sre; sh_sim[wrp] = sim;
                     sh_cre[wrp] = cre; sh_cim[wrp] = cim; }
    __syncthreads();
    if (threadIdx.x == 0) {
        float a = 0.f, b = 0.f; int cc = 0, d = 0;
        #pragma unroll
        for (int i = 0; i < NTHR / 32; i++) {
            a += sh_sre[i]; b += sh_sim[i]; cc += sh_cre[i]; d += sh_cim[i];
        }
        part[blockIdx.x].sre = a; part[blockIdx.x].sim = b;
        part[blockIdx.x].cre = cc; part[blockIdx.x].cim = d;
    }
}

// Inline final reduce over a partial buffer; every block computes the
// identical fixed-order result (deterministic). Returns (s_re, s_im).
__device__ __forceinline__ float2 final_reduce(const Part* __restrict__ part,
                                               float* sh_s, int* sh_c,
                                               float2* sh_res) {
    float sre = 0.f, sim = 0.f; int cre = 0, cim = 0;
    for (int i = threadIdx.x; i < NBLK; i += NTHR) {
        Part p = part[i];
        sre += p.sre; sim += p.sim; cre += p.cre; cim += p.cim;
    }
    #pragma unroll
    for (int o = 16; o > 0; o >>= 1) {
        sre += __shfl_down_sync(0xffffffffu, sre, o);
        sim += __shfl_down_sync(0xffffffffu, sim, o);
        cre += __shfl_down_sync(0xffffffffu, cre, o);
        cim += __shfl_down_sync(0xffffffffu, cim, o);
    }
    int lane = threadIdx.x & 31, wrp = threadIdx.x >> 5;
    if (lane == 0) {
        sh_s[wrp] = sre; sh_s[8 + wrp] = sim;
        sh_c[wrp] = cre; sh_c[8 + wrp] = cim;
    }
    __syncthreads();
    if (threadIdx.x == 0) {
        float a = 0.f, b = 0.f; int cc = 0, d = 0;
        #pragma unroll
        for (int i = 0; i < 8; i++) {
            a += sh_s[i]; b += sh_s[8 + i]; cc += sh_c[i]; d += sh_c[8 + i];
        }
        sh_res->x = fmaxf(a / fmaxf((float)cc, 1.0f), 1e-6f);
        sh_res->y = fmaxf(b / fmaxf((float)d, 1.0f), 1e-6f);
    }
    __syncthreads();
    return *sh_res;
}

// ---------------- Pass 1: stats of raw w -> g_part1 ----------------
__global__ void __launch_bounds__(NTHR, 6)
k_pass1(const float* __restrict__ re, const float* __restrict__ im, int n) {
    float sre = 0.f, sim = 0.f; int cre = 0, cim = 0;
    int gtid = blockIdx.x * NTHR + threadIdx.x;
    int stride = gridDim.x * NTHR;
    int n4 = n >> 2;
    const float4* re4 = reinterpret_cast<const float4*>(re);
    const float4* im4 = reinterpret_cast<const float4*>(im);
    int i = gtid;
    for (; i + stride < n4; i += 2 * stride) {
        float4 a0 = re4[i], b0 = im4[i];
        float4 a1 = re4[i + stride], b1 = im4[i + stride];
        acc_stats(a0.x, b0.x, sre, sim, cre, cim);
        acc_stats(a0.y, b0.y, sre, sim, cre, cim);
        acc_stats(a0.z, b0.z, sre, sim, cre, cim);
        acc_stats(a0.w, b0.w, sre, sim, cre, cim);
        acc_stats(a1.x, b1.x, sre, sim, cre, cim);
        acc_stats(a1.y, b1.y, sre, sim, cre, cim);
        acc_stats(a1.z, b1.z, sre, sim, cre, cim);
        acc_stats(a1.w, b1.w, sre, sim, cre, cim);
    }
    if (i < n4) {
        float4 a0 = re4[i], b0 = im4[i];
        acc_stats(a0.x, b0.x, sre, sim, cre, cim);
        acc_stats(a0.y, b0.y, sre, sim, cre, cim);
        acc_stats(a0.z, b0.z, sre, sim, cre, cim);
        acc_stats(a0.w, b0.w, sre, sim, cre, cim);
    }
    for (int j = (n4 << 2) + gtid; j < n; j += stride)
        acc_stats(re[j], im[j], sre, sim, cre, cim);
    stats_reduce_store(g_part1, sre, sim, cre, cim);
}

// ------- Pass 2: s1 = reduce(g_part1); stats of err1 -> g_part2 -------
__global__ void __launch_bounds__(NTHR, 6)
k_pass2(const float* __restrict__ re, const float* __restrict__ im,
        const float* __restrict__ temp, int n) {
    __shared__ float  sh_s[16];
    __shared__ int    sh_c[16];
    __shared__ float2 sh_res;
    float2 s1 = final_reduce(g_part1, sh_s, sh_c, &sh_res);
    Coef c = make_coef(temp);

    float sre = 0.f, sim = 0.f; int cre = 0, cim = 0;
    int gtid = blockIdx.x * NTHR + threadIdx.x;
    int stride = gridDim.x * NTHR;
    int n4 = n >> 2;
    const float4* re4 = reinterpret_cast<const float4*>(re);
    const float4* im4 = reinterpret_cast<const float4*>(im);

    auto body = [&](const float4& a, const float4& b) {
        float qr, qi;
        quant_eval(a.x, b.x, s1.x, s1.y, c, qr, qi);
        acc_stats(a.x - qr, b.x - qi, sre, sim, cre, cim);
        quant_eval(a.y, b.y, s1.x, s1.y, c, qr, qi);
        acc_stats(a.y - qr, b.y - qi, sre, sim, cre, cim);
        quant_eval(a.z, b.z, s1.x, s1.y, c, qr, qi);
        acc_stats(a.z - qr, b.z - qi, sre, sim, cre, cim);
        quant_eval(a.w, b.w, s1.x, s1.y, c, qr, qi);
        acc_stats(a.w - qr, b.w - qi, sre, sim, cre, cim);
    };

    int i = gtid;
    for (; i + stride < n4; i += 2 * stride) {
        float4 a0 = re4[i], b0 = im4[i];
        float4 a1 = re4[i + stride], b1 = im4[i + stride];
        body(a0, b0);
        body(a1, b1);
    }
    if (i < n4) {
        float4 a0 = re4[i], b0 = im4[i];
        body(a0, b0);
    }
    for (int j = (n4 << 2) + gtid; j < n; j += stride) {
        float qr, qi;
        quant_eval(re[j], im[j], s1.x, s1.y, c, qr, qi);
        acc_stats(re[j] - qr, im[j] - qi, sre, sim, cre, cim);
    }
    stats_reduce_store(g_part2, sre, sim, cre, cim);
}

// ------- Pass 3: s1,s2 reduces; out = q1 + q2 -------
__global__ void __launch_bounds__(NTHR, 6)
k_pass3(const float* __restrict__ re, const float* __restrict__ im,
        const float* __restrict__ temp,
        float* __restrict__ out_re, float* __restrict__ out_im, int n) {
    __shared__ float  sh_s[16];
    __shared__ int    sh_c[16];
    __shared__ float2 sh_res1, sh_res2;
    float2 s1 = final_reduce(g_part1, sh_s, sh_c, &sh_res1);
    __syncthreads();   // reuse of sh_s/sh_c between the two reduces
    float2 s2 = final_reduce(g_part2, sh_s, sh_c, &sh_res2);
    Coef c = make_coef(temp);

    int gtid = blockIdx.x * NTHR + threadIdx.x;
    int stride = gridDim.x * NTHR;
    int n4 = n >> 2;
    const float4* re4 = reinterpret_cast<const float4*>(re);
    const float4* im4 = reinterpret_cast<const float4*>(im);
    float4* or4 = reinterpret_cast<float4*>(out_re);
    float4* oi4 = reinterpret_cast<float4*>(out_im);

    auto body = [&](const float4& a, const float4& b, float4& qr4, float4& qi4) {
        float q1r, q1i, q2r, q2i;
        quant_eval(a.x, b.x, s1.x, s1.y, c, q1r, q1i);
        quant_eval(a.x - q1r, b.x - q1i, s2.x, s2.y, c, q2r, q2i);
        qr4.x = q1r + q2r; qi4.x = q1i + q2i;
        quant_eval(a.y, b.y, s1.x, s1.y, c, q1r, q1i);
        quant_eval(a.y - q1r, b.y - q1i, s2.x, s2.y, c, q2r, q2i);
        qr4.y = q1r + q2r; qi4.y = q1i + q2i;
        quant_eval(a.z, b.z, s1.x, s1.y, c, q1r, q1i);
        quant_eval(a.z - q1r, b.z - q1i, s2.x, s2.y, c, q2r, q2i);
        qr4.z = q1r + q2r; qi4.z = q1i + q2i;
        quant_eval(a.w, b.w, s1.x, s1.y, c, q1r, q1i);
        quant_eval(a.w - q1r, b.w - q1i, s2.x, s2.y, c, q2r, q2i);
        qr4.w = q1r + q2r; qi4.w = q1i + q2i;
    };

    int i = gtid;
    for (; i + stride < n4; i += 2 * stride) {
        float4 a0 = re4[i], b0 = im4[i];
        float4 a1 = re4[i + stride], b1 = im4[i + stride];
        float4 qr4, qi4;
        body(a0, b0, qr4, qi4);
        or4[i] = qr4; oi4[i] = qi4;
        body(a1, b1, qr4, qi4);
        or4[i + stride] = qr4; oi4[i + stride] = qi4;
    }
    if (i < n4) {
        float4 a0 = re4[i], b0 = im4[i];
        float4 qr4, qi4;
        body(a0, b0, qr4, qi4);
        or4[i] = qr4; oi4[i] = qi4;
    }
    for (int j = (n4 << 2) + gtid; j < n; j += stride) {
        float q1r, q1i, q2r, q2i;
        quant_eval(re[j], im[j], s1.x, s1.y, c, q1r, q1i);
        quant_eval(re[j] - q1r, im[j] - q1i, s2.x, s2.y, c, q2r, q2i);
        out_re[j] = q1r + q2r;
        out_im[j] = q1i + q2i;
    }
}

extern "C" void kernel_launch(void* const* d_in, const int* in_sizes, int n_in,
                              void* d_out, int out_size) {
    const float* w_re = (const float*)d_in[0];
    const float* w_im = (const float*)d_in[1];
    const float* temp = (const float*)d_in[2];
    int n = in_sizes[0];
    float* out_re = (float*)d_out;
    float* out_im = out_re + n;

    k_pass1<<<NBLK, NTHR>>>(w_re, w_im, n);
    k_pass2<<<NBLK, NTHR>>>(w_re, w_im, temp, n);
    k_pass3<<<NBLK, NTHR>>>(w_re, w_im, temp, out_re, out_im, n);
}

// round 4
// speedup vs baseline: 1.1047x; 1.0274x over previous
#include <cuda_runtime.h>
#include <math.h>

// ---------------------------------------------------------------------------
// PhaseQuantizer: 2-step residual phase quantization, minimal-traffic plan.
//   pass1: masked abs-sum stats of w               (reads 8n bytes)
//   pass2: [inline reduce s1] eval q1, stats(err1)  (reads 8n)
//   pass3: [inline reduce s1,s2] q1,q2 -> out       (reads 8n, writes 8n)
// Eval: psi>=0 + E=e^2 factorization, 3 MUFU / ~27 instr.
// Loops: software-pipelined / 4x-unrolled, split accumulators, streaming
// cache hints (__ldcs/__stcs) since there is zero intra-pass reuse.
// ---------------------------------------------------------------------------

namespace {
constexpr int   NBLK  = 1184;   // 8 * 148 SMs, one wave
constexpr int   NTHR  = 256;
constexpr float PI_F  = 3.14159265358979323846f;
constexpr float LOG2E = 1.44269504088896340736f;
}

struct Part { float sre, sim; int cre, cim; };
__device__ Part g_part1[NBLK];
__device__ Part g_part2[NBLK];

__device__ __forceinline__ float ex2f(float x) {
    float y; asm("ex2.approx.f32 %0, %1;" : "=f"(y) : "f"(x)); return y;
}
__device__ __forceinline__ float rcpf(float x) {
    float y; asm("rcp.approx.f32 %0, %1;" : "=f"(y) : "f"(x)); return y;
}

struct Coef {
    float p0, p1, p2, p3, p4;  // atan poly coeffs prescaled by (pi/t)*log2(e)
    float c1, c3;              // exp(-pi^2/(4t)), exp(-pi^2/t)
};

__device__ __forceinline__ Coef make_coef(const float* temp) {
    float t = __ldg(temp) + 1e-6f;
    float inv_t = 1.0f / t;
    float kl = PI_F * inv_t * LOG2E;
    Coef c;
    // Abramowitz & Stegun 4.4.49 atan poly (|x|<=1, |err|<=1e-5 rad)
    c.p0 =  0.9998660f * kl;
    c.p1 = -0.3302995f * kl;
    c.p2 =  0.1801410f * kl;
    c.p3 = -0.0851330f * kl;
    c.p4 =  0.0208351f * kl;
    c.c1 = __expf(-(PI_F * PI_F * 0.25f) * inv_t);
    c.c3 = c.c1 * c.c1; c.c3 = c.c3 * c.c3;
    return c;
}

// Soft phase quantization; 3 MUFU (rcp, ex2, rcp).
__device__ __forceinline__ void quant_eval(float re, float im,
                                           float sre, float sim,
                                           const Coef& c,
                                           float& qre, float& qim) {
    float ar = fabsf(re), ai = fabsf(im);
    bool  rd = (ar >= ai);
    float m  = fmaxf(fmaxf(ar, ai), 1e-30f);
    float nm = fminf(ar, ai);
    float r  = nm * rcpf(m);               // in [0,1]
    float r2 = r * r;
    float p  = fmaf(r2, c.p4, c.p3);
    p = fmaf(r2, p, c.p2);
    p = fmaf(r2, p, c.p1);
    p = fmaf(r2, p, c.p0);
    float v  = r * p;                       // (pi/t)*log2e * psi  (>= 0)
    float e  = ex2f(v);                     // exp(pi*psi/t) >= 1
    float E  = e * e;
    float uo = c.c3 * E;
    float t2 = fmaf(e, uo, e);              // e*(1+uo)
    float eD = fmaf(c.c1, E + 1.0f, t2);    // e * softmax denominator
    float rD = rcpf(eD);
    float P  = fmaf(2.0f, e, -t2) * rD;     // p_near - p_opposite (even)
    float Qa = fmaf(c.c1, E, -c.c1) * rD;   // p_+90 - p_-90 (|odd|)
    float mins = rd ? im : re;
    float majs = rd ? re : im;
    float Q  = copysignf(Qa, mins);
    float qa = copysignf(P, majs);
    float u  = rd ? qa : Q;
    float w  = rd ? Q  : qa;
    qre = u * sre;
    qim = w * sim;
}

__device__ __forceinline__ void acc_stats(float re, float im,
                                          float& sre, float& sim,
                                          int& cre, int& cim) {
    float ar = fabsf(re), ai = fabsf(im);
    if (ar >= ai) { sre += ar; cre++; }
    else          { sim += ai; cim++; }
}

// Deterministic fixed-order block reduce -> per-block partial slot.
__device__ __forceinline__ void stats_reduce_store(Part* part,
                                                   float sre, float sim,
                                                   int cre, int cim) {
    #pragma unroll
    for (int o = 16; o > 0; o >>= 1) {
        sre += __shfl_down_sync(0xffffffffu, sre, o);
        sim += __shfl_down_sync(0xffffffffu, sim, o);
        cre += __shfl_down_sync(0xffffffffu, cre, o);
        cim += __shfl_down_sync(0xffffffffu, cim, o);
    }
    __shared__ float sh_sre[NTHR / 32], sh_sim[NTHR / 32];
    __shared__ int   sh_cre[NTHR / 32], sh_cim[NTHR / 32];
    int lane = threadIdx.x & 31, wrp = threadIdx.x >> 5;
    if (lane == 0) { sh_sre[wrp] = sre; sh_sim[wrp] = sim;
                     sh_cre[wrp] = cre; sh_cim[wrp] = cim; }
    __syncthreads();
    if (threadIdx.x == 0) {
        float a = 0.f, b = 0.f; int cc = 0, d = 0;
        #pragma unroll
        for (int i = 0; i < NTHR / 32; i++) {
            a += sh_sre[i]; b += sh_sim[i]; cc += sh_cre[i]; d += sh_cim[i];
        }
        part[blockIdx.x].sre = a; part[blockIdx.x].sim = b;
        part[blockIdx.x].cre = cc; part[blockIdx.x].cim = d;
    }
}

// Inline final reduce over a partial buffer; every block computes the
// identical fixed-order result (deterministic). Returns (s_re, s_im).
__device__ __forceinline__ float2 final_reduce(const Part* __restrict__ part,
                                               float* sh_s, int* sh_c,
                                               float2* sh_res) {
    float sre = 0.f, sim = 0.f; int cre = 0, cim = 0;
    for (int i = threadIdx.x; i < NBLK; i += NTHR) {
        Part p = part[i];
        sre += p.sre; sim += p.sim; cre += p.cre; cim += p.cim;
    }
    #pragma unroll
    for (int o = 16; o > 0; o >>= 1) {
        sre += __shfl_down_sync(0xffffffffu, sre, o);
        sim += __shfl_down_sync(0xffffffffu, sim, o);
        cre += __shfl_down_sync(0xffffffffu, cre, o);
        cim += __shfl_down_sync(0xffffffffu, cim, o);
    }
    int lane = threadIdx.x & 31, wrp = threadIdx.x >> 5;
    if (lane == 0) {
        sh_s[wrp] = sre; sh_s[8 + wrp] = sim;
        sh_c[wrp] = cre; sh_c[8 + wrp] = cim;
    }
    __syncthreads();
    if (threadIdx.x == 0) {
        float a = 0.f, b = 0.f; int cc = 0, d = 0;
        #pragma unroll
        for (int i = 0; i < 8; i++) {
            a += sh_s[i]; b += sh_s[8 + i]; cc += sh_c[i]; d += sh_c[8 + i];
        }
        sh_res->x = fmaxf(a / fmaxf((float)cc, 1.0f), 1e-6f);
        sh_res->y = fmaxf(b / fmaxf((float)d, 1.0f), 1e-6f);
    }
    __syncthreads();
    return *sh_res;
}

// ---------------- Pass 1: stats of raw w -> g_part1 ----------------
__global__ void __launch_bounds__(NTHR, 6)
k_pass1(const float* __restrict__ re, const float* __restrict__ im, int n) {
    float s0re = 0.f, s0im = 0.f, s1re = 0.f, s1im = 0.f;
    int   c0re = 0, c0im = 0, c1re = 0, c1im = 0;
    int gtid = blockIdx.x * NTHR + threadIdx.x;
    int stride = gridDim.x * NTHR;
    int n4 = n >> 2;
    const float4* re4 = reinterpret_cast<const float4*>(re);
    const float4* im4 = reinterpret_cast<const float4*>(im);
    int i = gtid;
    // 4x unrolled: 8 x 16B loads in flight before any consumption
    for (; i + 3 * stride < n4; i += 4 * stride) {
        float4 a0 = __ldcs(&re4[i]);
        float4 a1 = __ldcs(&re4[i + stride]);
        float4 a2 = __ldcs(&re4[i + 2 * stride]);
        float4 a3 = __ldcs(&re4[i + 3 * stride]);
        float4 b0 = __ldcs(&im4[i]);
        float4 b1 = __ldcs(&im4[i + stride]);
        float4 b2 = __ldcs(&im4[i + 2 * stride]);
        float4 b3 = __ldcs(&im4[i + 3 * stride]);
        acc_stats(a0.x, b0.x, s0re, s0im, c0re, c0im);
        acc_stats(a0.y, b0.y, s1re, s1im, c1re, c1im);
        acc_stats(a0.z, b0.z, s0re, s0im, c0re, c0im);
        acc_stats(a0.w, b0.w, s1re, s1im, c1re, c1im);
        acc_stats(a1.x, b1.x, s0re, s0im, c0re, c0im);
        acc_stats(a1.y, b1.y, s1re, s1im, c1re, c1im);
        acc_stats(a1.z, b1.z, s0re, s0im, c0re, c0im);
        acc_stats(a1.w, b1.w, s1re, s1im, c1re, c1im);
        acc_stats(a2.x, b2.x, s0re, s0im, c0re, c0im);
        acc_stats(a2.y, b2.y, s1re, s1im, c1re, c1im);
        acc_stats(a2.z, b2.z, s0re, s0im, c0re, c0im);
        acc_stats(a2.w, b2.w, s1re, s1im, c1re, c1im);
        acc_stats(a3.x, b3.x, s0re, s0im, c0re, c0im);
        acc_stats(a3.y, b3.y, s1re, s1im, c1re, c1im);
        acc_stats(a3.z, b3.z, s0re, s0im, c0re, c0im);
        acc_stats(a3.w, b3.w, s1re, s1im, c1re, c1im);
    }
    for (; i < n4; i += stride) {
        float4 a0 = __ldcs(&re4[i]), b0 = __ldcs(&im4[i]);
        acc_stats(a0.x, b0.x, s0re, s0im, c0re, c0im);
        acc_stats(a0.y, b0.y, s1re, s1im, c1re, c1im);
        acc_stats(a0.z, b0.z, s0re, s0im, c0re, c0im);
        acc_stats(a0.w, b0.w, s1re, s1im, c1re, c1im);
    }
    for (int j = (n4 << 2) + gtid; j < n; j += stride)
        acc_stats(re[j], im[j], s0re, s0im, c0re, c0im);
    stats_reduce_store(g_part1, s0re + s1re, s0im + s1im,
                       c0re + c1re, c0im + c1im);
}

// ------- Pass 2: s1 = reduce(g_part1); stats of err1 -> g_part2 -------
__global__ void __launch_bounds__(NTHR, 6)
k_pass2(const float* __restrict__ re, const float* __restrict__ im,
        const float* __restrict__ temp, int n) {
    __shared__ float  sh_s[16];
    __shared__ int    sh_c[16];
    __shared__ float2 sh_res;
    float2 s1 = final_reduce(g_part1, sh_s, sh_c, &sh_res);
    Coef c = make_coef(temp);

    float s0re = 0.f, s0im = 0.f, s1re_ = 0.f, s1im_ = 0.f;
    int   c0re = 0, c0im = 0, c1re = 0, c1im = 0;
    int gtid = blockIdx.x * NTHR + threadIdx.x;
    int stride = gridDim.x * NTHR;
    int n4 = n >> 2;
    const float4* re4 = reinterpret_cast<const float4*>(re);
    const float4* im4 = reinterpret_cast<const float4*>(im);

    auto body = [&](const float4& a, const float4& b) {
        float qr, qi;
        quant_eval(a.x, b.x, s1.x, s1.y, c, qr, qi);
        acc_stats(a.x - qr, b.x - qi, s0re, s0im, c0re, c0im);
        quant_eval(a.y, b.y, s1.x, s1.y, c, qr, qi);
        acc_stats(a.y - qr, b.y - qi, s1re_, s1im_, c1re, c1im);
        quant_eval(a.z, b.z, s1.x, s1.y, c, qr, qi);
        acc_stats(a.z - qr, b.z - qi, s0re, s0im, c0re, c0im);
        quant_eval(a.w, b.w, s1.x, s1.y, c, qr, qi);
        acc_stats(a.w - qr, b.w - qi, s1re_, s1im_, c1re, c1im);
    };

    int i = gtid;
    if (i < n4) {
        float4 a0 = __ldcs(&re4[i]), b0 = __ldcs(&im4[i]);
        // software pipeline: issue next iter's loads before current body
        for (; i + stride < n4; i += stride) {
            float4 a1 = __ldcs(&re4[i + stride]);
            float4 b1 = __ldcs(&im4[i + stride]);
            body(a0, b0);
            a0 = a1; b0 = b1;
        }
        body(a0, b0);
    }
    for (int j = (n4 << 2) + gtid; j < n; j += stride) {
        float qr, qi;
        quant_eval(re[j], im[j], s1.x, s1.y, c, qr, qi);
        acc_stats(re[j] - qr, im[j] - qi, s0re, s0im, c0re, c0im);
    }
    stats_reduce_store(g_part2, s0re + s1re_, s0im + s1im_,
                       c0re + c1re, c0im + c1im);
}

// ------- Pass 3: s1,s2 reduces; out = q1 + q2 -------
__global__ void __launch_bounds__(NTHR, 6)
k_pass3(const float* __restrict__ re, const float* __restrict__ im,
        const float* __restrict__ temp,
        float* __restrict__ out_re, float* __restrict__ out_im, int n) {
    __shared__ float  sh_s[16];
    __shared__ int    sh_c[16];
    __shared__ float2 sh_res1, sh_res2;
    float2 s1 = final_reduce(g_part1, sh_s, sh_c, &sh_res1);
    __syncthreads();
    float2 s2 = final_reduce(g_part2, sh_s, sh_c, &sh_res2);
    Coef c = make_coef(temp);

    int gtid = blockIdx.x * NTHR + threadIdx.x;
    int stride = gridDim.x * NTHR;
    int n4 = n >> 2;
    const float4* re4 = reinterpret_cast<const float4*>(re);
    const float4* im4 = reinterpret_cast<const float4*>(im);
    float4* or4 = reinterpret_cast<float4*>(out_re);
    float4* oi4 = reinterpret_cast<float4*>(out_im);

    auto body = [&](const float4& a, const float4& b, float4& qr4, float4& qi4) {
        float q1r, q1i, q2r, q2i;
        quant_eval(a.x, b.x, s1.x, s1.y, c, q1r, q1i);
        quant_eval(a.x - q1r, b.x - q1i, s2.x, s2.y, c, q2r, q2i);
        qr4.x = q1r + q2r; qi4.x = q1i + q2i;
        quant_eval(a.y, b.y, s1.x, s1.y, c, q1r, q1i);
        quant_eval(a.y - q1r, b.y - q1i, s2.x, s2.y, c, q2r, q2i);
        qr4.y = q1r + q2r; qi4.y = q1i + q2i;
        quant_eval(a.z, b.z, s1.x, s1.y, c, q1r, q1i);
        quant_eval(a.z - q1r, b.z - q1i, s2.x, s2.y, c, q2r, q2i);
        qr4.z = q1r + q2r; qi4.z = q1i + q2i;
        quant_eval(a.w, b.w, s1.x, s1.y, c, q1r, q1i);
        quant_eval(a.w - q1r, b.w - q1i, s2.x, s2.y, c, q2r, q2i);
        qr4.w = q1r + q2r; qi4.w = q1i + q2i;
    };

    int i = gtid;
    if (i < n4) {
        float4 a0 = __ldcs(&re4[i]), b0 = __ldcs(&im4[i]);
        for (; i + stride < n4; i += stride) {
            float4 a1 = __ldcs(&re4[i + stride]);
            float4 b1 = __ldcs(&im4[i + stride]);
            float4 qr4, qi4;
            body(a0, b0, qr4, qi4);
            __stcs(&or4[i], qr4);
            __stcs(&oi4[i], qi4);
            a0 = a1; b0 = b1;
        }
        float4 qr4, qi4;
        body(a0, b0, qr4, qi4);
        __stcs(&or4[i], qr4);
        __stcs(&oi4[i], qi4);
    }
    for (int j = (n4 << 2) + gtid; j < n; j += stride) {
        float q1r, q1i, q2r, q2i;
        quant_eval(re[j], im[j], s1.x, s1.y, c, q1r, q1i);
        quant_eval(re[j] - q1r, im[j] - q1i, s2.x, s2.y, c, q2r, q2i);
        out_re[j] = q1r + q2r;
        out_im[j] = q1i + q2i;
    }
}

extern "C" void kernel_launch(void* const* d_in, const int* in_sizes, int n_in,
                              void* d_out, int out_size) {
    const float* w_re = (const float*)d_in[0];
    const float* w_im = (const float*)d_in[1];
    const float* temp = (const float*)d_in[2];
    int n = in_sizes[0];
    float* out_re = (float*)d_out;
    float* out_im = out_re + n;

    k_pass1<<<NBLK, NTHR>>>(w_re, w_im, n);
    k_pass2<<<NBLK, NTHR>>>(w_re, w_im, temp, n);
    k_pass3<<<NBLK, NTHR>>>(w_re, w_im, temp, out_re, out_im, n);
}

// round 5
// speedup vs baseline: 1.1611x; 1.0511x over previous
#include <cuda_runtime.h>
#include <math.h>

// ---------------------------------------------------------------------------
// PhaseQuantizer: 2-step residual phase quantization, minimal-traffic plan.
//   pass1: masked abs-sum stats of w               (reads 8n bytes)
//   pass2: [inline reduce s1] eval q1, stats(err1)  (reads 8n)
//   pass3: [inline reduce s1,s2] q1,q2 -> out       (reads 8n, writes 8n)
// Eval: psi>=0 + E=e^2 factorization, 3 MUFU / ~27 instr.
// Pass2/3: 2-group bodies with 2-group prefetch (4x16B loads in flight per
// thread through every body) to cover DRAM latency under long eval chains.
// ---------------------------------------------------------------------------

namespace {
constexpr int   NBLK  = 1184;   // 8 * 148 SMs
constexpr int   NTHR  = 256;
constexpr float PI_F  = 3.14159265358979323846f;
constexpr float LOG2E = 1.44269504088896340736f;
}

struct Part { float sre, sim; int cre, cim; };
__device__ Part g_part1[NBLK];
__device__ Part g_part2[NBLK];

__device__ __forceinline__ float ex2f(float x) {
    float y; asm("ex2.approx.f32 %0, %1;" : "=f"(y) : "f"(x)); return y;
}
__device__ __forceinline__ float rcpf(float x) {
    float y; asm("rcp.approx.f32 %0, %1;" : "=f"(y) : "f"(x)); return y;
}

struct Coef {
    float p0, p1, p2, p3, p4;  // atan poly coeffs prescaled by (pi/t)*log2(e)
    float c1, c3;              // exp(-pi^2/(4t)), exp(-pi^2/t)
};

__device__ __forceinline__ Coef make_coef(const float* temp) {
    float t = __ldg(temp) + 1e-6f;
    float inv_t = 1.0f / t;
    float kl = PI_F * inv_t * LOG2E;
    Coef c;
    // Abramowitz & Stegun 4.4.49 atan poly (|x|<=1, |err|<=1e-5 rad)
    c.p0 =  0.9998660f * kl;
    c.p1 = -0.3302995f * kl;
    c.p2 =  0.1801410f * kl;
    c.p3 = -0.0851330f * kl;
    c.p4 =  0.0208351f * kl;
    c.c1 = __expf(-(PI_F * PI_F * 0.25f) * inv_t);
    c.c3 = c.c1 * c.c1; c.c3 = c.c3 * c.c3;
    return c;
}

// Soft phase quantization; 3 MUFU (rcp, ex2, rcp).
__device__ __forceinline__ void quant_eval(float re, float im,
                                           float sre, float sim,
                                           const Coef& c,
                                           float& qre, float& qim) {
    float ar = fabsf(re), ai = fabsf(im);
    bool  rd = (ar >= ai);
    float m  = fmaxf(fmaxf(ar, ai), 1e-30f);
    float nm = fminf(ar, ai);
    float r  = nm * rcpf(m);               // in [0,1]
    float r2 = r * r;
    float p  = fmaf(r2, c.p4, c.p3);
    p = fmaf(r2, p, c.p2);
    p = fmaf(r2, p, c.p1);
    p = fmaf(r2, p, c.p0);
    float v  = r * p;                       // (pi/t)*log2e * psi  (>= 0)
    float e  = ex2f(v);                     // exp(pi*psi/t) >= 1
    float E  = e * e;
    float uo = c.c3 * E;
    float t2 = fmaf(e, uo, e);              // e*(1+uo)
    float eD = fmaf(c.c1, E + 1.0f, t2);    // e * softmax denominator
    float rD = rcpf(eD);
    float P  = fmaf(2.0f, e, -t2) * rD;     // p_near - p_opposite (even)
    float Qa = fmaf(c.c1, E, -c.c1) * rD;   // p_+90 - p_-90 (|odd|)
    float mins = rd ? im : re;
    float majs = rd ? re : im;
    float Q  = copysignf(Qa, mins);
    float qa = copysignf(P, majs);
    float u  = rd ? qa : Q;
    float w  = rd ? Q  : qa;
    qre = u * sre;
    qim = w * sim;
}

__device__ __forceinline__ void acc_stats(float re, float im,
                                          float& sre, float& sim,
                                          int& cre, int& cim) {
    float ar = fabsf(re), ai = fabsf(im);
    if (ar >= ai) { sre += ar; cre++; }
    else          { sim += ai; cim++; }
}

// Deterministic fixed-order block reduce -> per-block partial slot.
__device__ __forceinline__ void stats_reduce_store(Part* part,
                                                   float sre, float sim,
                                                   int cre, int cim) {
    #pragma unroll
    for (int o = 16; o > 0; o >>= 1) {
        sre += __shfl_down_sync(0xffffffffu, sre, o);
        sim += __shfl_down_sync(0xffffffffu, sim, o);
        cre += __shfl_down_sync(0xffffffffu, cre, o);
        cim += __shfl_down_sync(0xffffffffu, cim, o);
    }
    __shared__ float sh_sre[NTHR / 32], sh_sim[NTHR / 32];
    __shared__ int   sh_cre[NTHR / 32], sh_cim[NTHR / 32];
    int lane = threadIdx.x & 31, wrp = threadIdx.x >> 5;
    if (lane == 0) { sh_sre[wrp] = sre; sh_sim[wrp] = sim;
                     sh_cre[wrp] = cre; sh_cim[wrp] = cim; }
    __syncthreads();
    if (threadIdx.x == 0) {
        float a = 0.f, b = 0.f; int cc = 0, d = 0;
        #pragma unroll
        for (int i = 0; i < NTHR / 32; i++) {
            a += sh_sre[i]; b += sh_sim[i]; cc += sh_cre[i]; d += sh_cim[i];
        }
        part[blockIdx.x].sre = a; part[blockIdx.x].sim = b;
        part[blockIdx.x].cre = cc; part[blockIdx.x].cim = d;
    }
}

// Inline final reduce over a partial buffer; every block computes the
// identical fixed-order result (deterministic). Returns (s_re, s_im).
__device__ __forceinline__ float2 final_reduce(const Part* __restrict__ part,
                                               float* sh_s, int* sh_c,
                                               float2* sh_res) {
    float sre = 0.f, sim = 0.f; int cre = 0, cim = 0;
    for (int i = threadIdx.x; i < NBLK; i += NTHR) {
        Part p = part[i];
        sre += p.sre; sim += p.sim; cre += p.cre; cim += p.cim;
    }
    #pragma unroll
    for (int o = 16; o > 0; o >>= 1) {
        sre += __shfl_down_sync(0xffffffffu, sre, o);
        sim += __shfl_down_sync(0xffffffffu, sim, o);
        cre += __shfl_down_sync(0xffffffffu, cre, o);
        cim += __shfl_down_sync(0xffffffffu, cim, o);
    }
    int lane = threadIdx.x & 31, wrp = threadIdx.x >> 5;
    if (lane == 0) {
        sh_s[wrp] = sre; sh_s[8 + wrp] = sim;
        sh_c[wrp] = cre; sh_c[8 + wrp] = cim;
    }
    __syncthreads();
    if (threadIdx.x == 0) {
        float a = 0.f, b = 0.f; int cc = 0, d = 0;
        #pragma unroll
        for (int i = 0; i < 8; i++) {
            a += sh_s[i]; b += sh_s[8 + i]; cc += sh_c[i]; d += sh_c[8 + i];
        }
        sh_res->x = fmaxf(a / fmaxf((float)cc, 1.0f), 1e-6f);
        sh_res->y = fmaxf(b / fmaxf((float)d, 1.0f), 1e-6f);
    }
    __syncthreads();
    return *sh_res;
}

// ---------------- Pass 1: stats of raw w -> g_part1 ----------------
__global__ void __launch_bounds__(NTHR, 6)
k_pass1(const float* __restrict__ re, const float* __restrict__ im, int n) {
    float s0re = 0.f, s0im = 0.f, s1re = 0.f, s1im = 0.f;
    int   c0re = 0, c0im = 0, c1re = 0, c1im = 0;
    int gtid = blockIdx.x * NTHR + threadIdx.x;
    int stride = gridDim.x * NTHR;
    int n4 = n >> 2;
    const float4* re4 = reinterpret_cast<const float4*>(re);
    const float4* im4 = reinterpret_cast<const float4*>(im);
    int i = gtid;
    for (; i + 3 * stride < n4; i += 4 * stride) {
        float4 a0 = __ldcs(&re4[i]);
        float4 a1 = __ldcs(&re4[i + stride]);
        float4 a2 = __ldcs(&re4[i + 2 * stride]);
        float4 a3 = __ldcs(&re4[i + 3 * stride]);
        float4 b0 = __ldcs(&im4[i]);
        float4 b1 = __ldcs(&im4[i + stride]);
        float4 b2 = __ldcs(&im4[i + 2 * stride]);
        float4 b3 = __ldcs(&im4[i + 3 * stride]);
        acc_stats(a0.x, b0.x, s0re, s0im, c0re, c0im);
        acc_stats(a0.y, b0.y, s1re, s1im, c1re, c1im);
        acc_stats(a0.z, b0.z, s0re, s0im, c0re, c0im);
        acc_stats(a0.w, b0.w, s1re, s1im, c1re, c1im);
        acc_stats(a1.x, b1.x, s0re, s0im, c0re, c0im);
        acc_stats(a1.y, b1.y, s1re, s1im, c1re, c1im);
        acc_stats(a1.z, b1.z, s0re, s0im, c0re, c0im);
        acc_stats(a1.w, b1.w, s1re, s1im, c1re, c1im);
        acc_stats(a2.x, b2.x, s0re, s0im, c0re, c0im);
        acc_stats(a2.y, b2.y, s1re, s1im, c1re, c1im);
        acc_stats(a2.z, b2.z, s0re, s0im, c0re, c0im);
        acc_stats(a2.w, b2.w, s1re, s1im, c1re, c1im);
        acc_stats(a3.x, b3.x, s0re, s0im, c0re, c0im);
        acc_stats(a3.y, b3.y, s1re, s1im, c1re, c1im);
        acc_stats(a3.z, b3.z, s0re, s0im, c0re, c0im);
        acc_stats(a3.w, b3.w, s1re, s1im, c1re, c1im);
    }
    for (; i < n4; i += stride) {
        float4 a0 = __ldcs(&re4[i]), b0 = __ldcs(&im4[i]);
        acc_stats(a0.x, b0.x, s0re, s0im, c0re, c0im);
        acc_stats(a0.y, b0.y, s1re, s1im, c1re, c1im);
        acc_stats(a0.z, b0.z, s0re, s0im, c0re, c0im);
        acc_stats(a0.w, b0.w, s1re, s1im, c1re, c1im);
    }
    for (int j = (n4 << 2) + gtid; j < n; j += stride)
        acc_stats(re[j], im[j], s0re, s0im, c0re, c0im);
    stats_reduce_store(g_part1, s0re + s1re, s0im + s1im,
                       c0re + c1re, c0im + c1im);
}

// ------- Pass 2: s1 = reduce(g_part1); stats of err1 -> g_part2 -------
__global__ void __launch_bounds__(NTHR)
k_pass2(const float* __restrict__ re, const float* __restrict__ im,
        const float* __restrict__ temp, int n) {
    __shared__ float  sh_s[16];
    __shared__ int    sh_c[16];
    __shared__ float2 sh_res;
    float2 s1 = final_reduce(g_part1, sh_s, sh_c, &sh_res);
    Coef c = make_coef(temp);

    float s0re = 0.f, s0im = 0.f, s1re_ = 0.f, s1im_ = 0.f;
    int   c0re = 0, c0im = 0, c1re = 0, c1im = 0;
    int gtid = blockIdx.x * NTHR + threadIdx.x;
    int stride = gridDim.x * NTHR;
    int n4 = n >> 2;
    const float4* re4 = reinterpret_cast<const float4*>(re);
    const float4* im4 = reinterpret_cast<const float4*>(im);

    auto body = [&](const float4& a, const float4& b) {
        float qr, qi;
        quant_eval(a.x, b.x, s1.x, s1.y, c, qr, qi);
        acc_stats(a.x - qr, b.x - qi, s0re, s0im, c0re, c0im);
        quant_eval(a.y, b.y, s1.x, s1.y, c, qr, qi);
        acc_stats(a.y - qr, b.y - qi, s1re_, s1im_, c1re, c1im);
        quant_eval(a.z, b.z, s1.x, s1.y, c, qr, qi);
        acc_stats(a.z - qr, b.z - qi, s0re, s0im, c0re, c0im);
        quant_eval(a.w, b.w, s1.x, s1.y, c, qr, qi);
        acc_stats(a.w - qr, b.w - qi, s1re_, s1im_, c1re, c1im);
    };

    int i = gtid;
    if (i + stride < n4) {
        // 2-group pipeline: keep 4x16B loads in flight through each body pair
        float4 a0 = __ldcs(&re4[i]),          b0 = __ldcs(&im4[i]);
        float4 a1 = __ldcs(&re4[i + stride]), b1 = __ldcs(&im4[i + stride]);
        for (; i + 3 * stride < n4; i += 2 * stride) {
            float4 a2 = __ldcs(&re4[i + 2 * stride]);
            float4 b2 = __ldcs(&im4[i + 2 * stride]);
            float4 a3 = __ldcs(&re4[i + 3 * stride]);
            float4 b3 = __ldcs(&im4[i + 3 * stride]);
            body(a0, b0);
            body(a1, b1);
            a0 = a2; b0 = b2; a1 = a3; b1 = b3;
        }
        body(a0, b0);
        body(a1, b1);
        i += 2 * stride;
    }
    for (; i < n4; i += stride) {
        float4 a = __ldcs(&re4[i]), b = __ldcs(&im4[i]);
        body(a, b);
    }
    for (int j = (n4 << 2) + gtid; j < n; j += stride) {
        float qr, qi;
        quant_eval(re[j], im[j], s1.x, s1.y, c, qr, qi);
        acc_stats(re[j] - qr, im[j] - qi, s0re, s0im, c0re, c0im);
    }
    stats_reduce_store(g_part2, s0re + s1re_, s0im + s1im_,
                       c0re + c1re, c0im + c1im);
}

// ------- Pass 3: s1,s2 reduces; out = q1 + q2 -------
__global__ void __launch_bounds__(NTHR)
k_pass3(const float* __restrict__ re, const float* __restrict__ im,
        const float* __restrict__ temp,
        float* __restrict__ out_re, float* __restrict__ out_im, int n) {
    __shared__ float  sh_s[16];
    __shared__ int    sh_c[16];
    __shared__ float2 sh_res1, sh_res2;
    float2 s1 = final_reduce(g_part1, sh_s, sh_c, &sh_res1);
    __syncthreads();
    float2 s2 = final_reduce(g_part2, sh_s, sh_c, &sh_res2);
    Coef c = make_coef(temp);

    int gtid = blockIdx.x * NTHR + threadIdx.x;
    int stride = gridDim.x * NTHR;
    int n4 = n >> 2;
    const float4* re4 = reinterpret_cast<const float4*>(re);
    const float4* im4 = reinterpret_cast<const float4*>(im);
    float4* or4 = reinterpret_cast<float4*>(out_re);
    float4* oi4 = reinterpret_cast<float4*>(out_im);

    auto body = [&](const float4& a, const float4& b, int idx) {
        float4 qr4, qi4;
        float q1r, q1i, q2r, q2i;
        quant_eval(a.x, b.x, s1.x, s1.y, c, q1r, q1i);
        quant_eval(a.x - q1r, b.x - q1i, s2.x, s2.y, c, q2r, q2i);
        qr4.x = q1r + q2r; qi4.x = q1i + q2i;
        quant_eval(a.y, b.y, s1.x, s1.y, c, q1r, q1i);
        quant_eval(a.y - q1r, b.y - q1i, s2.x, s2.y, c, q2r, q2i);
        qr4.y = q1r + q2r; qi4.y = q1i + q2i;
        quant_eval(a.z, b.z, s1.x, s1.y, c, q1r, q1i);
        quant_eval(a.z - q1r, b.z - q1i, s2.x, s2.y, c, q2r, q2i);
        qr4.z = q1r + q2r; qi4.z = q1i + q2i;
        quant_eval(a.w, b.w, s1.x, s1.y, c, q1r, q1i);
        quant_eval(a.w - q1r, b.w - q1i, s2.x, s2.y, c, q2r, q2i);
        qr4.w = q1r + q2r; qi4.w = q1i + q2i;
        __stcs(&or4[idx], qr4);
        __stcs(&oi4[idx], qi4);
    };

    int i = gtid;
    if (i + stride < n4) {
        float4 a0 = __ldcs(&re4[i]),          b0 = __ldcs(&im4[i]);
        float4 a1 = __ldcs(&re4[i + stride]), b1 = __ldcs(&im4[i + stride]);
        for (; i + 3 * stride < n4; i += 2 * stride) {
            float4 a2 = __ldcs(&re4[i + 2 * stride]);
            float4 b2 = __ldcs(&im4[i + 2 * stride]);
            float4 a3 = __ldcs(&re4[i + 3 * stride]);
            float4 b3 = __ldcs(&im4[i + 3 * stride]);
            body(a0, b0, i);
            body(a1, b1, i + stride);
            a0 = a2; b0 = b2; a1 = a3; b1 = b3;
        }
        body(a0, b0, i);
        body(a1, b1, i + stride);
        i += 2 * stride;
    }
    for (; i < n4; i += stride) {
        float4 a = __ldcs(&re4[i]), b = __ldcs(&im4[i]);
        body(a, b, i);
    }
    for (int j = (n4 << 2) + gtid; j < n; j += stride) {
        float q1r, q1i, q2r, q2i;
        quant_eval(re[j], im[j], s1.x, s1.y, c, q1r, q1i);
        quant_eval(re[j] - q1r, im[j] - q1i, s2.x, s2.y, c, q2r, q2i);
        out_re[j] = q1r + q2r;
        out_im[j] = q1i + q2i;
    }
}

extern "C" void kernel_launch(void* const* d_in, const int* in_sizes, int n_in,
                              void* d_out, int out_size) {
    const float* w_re = (const float*)d_in[0];
    const float* w_im = (const float*)d_in[1];
    const float* temp = (const float*)d_in[2];
    int n = in_sizes[0];
    float* out_re = (float*)d_out;
    float* out_im = out_re + n;

    k_pass1<<<NBLK, NTHR>>>(w_re, w_im, n);
    k_pass2<<<NBLK, NTHR>>>(w_re, w_im, temp, n);
    k_pass3<<<NBLK, NTHR>>>(w_re, w_im, temp, out_re, out_im, n);
}